// round 2
// baseline (speedup 1.0000x reference)
#include <cuda_runtime.h>
#include <cstdint>

// Problem constants (fixed by the reference)
#define IN_CH   4096
#define OUT_CH  4096
#define BATCH   8192

// SpMM tiling
#define CT      128                 // columns (IN_CH) per shared tile
#define CT_LOG  7
#define NTILE   (IN_CH / CT)        // 32 column tiles
#define BT      256                 // batch per CTA
#define RB      64                  // output rows per CTA (8 warps x 8 rows)
#define NKEY    (OUT_CH * NTILE)    // 131072 segment keys
#define MAXNNZ  (1 << 21)           // 2M (actual ~1.68M)

// Scratch (device globals: allocation-free per harness rules)
__device__ float g_xT[(size_t)IN_CH * BATCH];   // 128 MB transposed x: xT[col][b]
__device__ int2  g_packed[MAXNNZ];              // (col, weight_bits) per nnz
__device__ int   g_seg[NKEY + 1];               // segment pointers per (row, ctile)

// ---------------------------------------------------------------------------
// 1) Transpose x [BATCH, IN_CH] -> g_xT [IN_CH, BATCH]
//    32x32 tiles, 32x8 threads, padded smem, coalesced on both sides.
// ---------------------------------------------------------------------------
__global__ void k_transpose(const float* __restrict__ x) {
    __shared__ float tile[32][33];
    const int c0 = blockIdx.x * 32;
    const int b0 = blockIdx.y * 32;
    const int tx = threadIdx.x, ty = threadIdx.y;
#pragma unroll
    for (int j = 0; j < 4; j++)
        tile[ty + j * 8][tx] = x[(size_t)(b0 + ty + j * 8) * IN_CH + c0 + tx];
    __syncthreads();
#pragma unroll
    for (int j = 0; j < 4; j++)
        g_xT[(size_t)(c0 + ty + j * 8) * BATCH + b0 + tx] = tile[tx][ty + j * 8];
}

// ---------------------------------------------------------------------------
// 2) Pack (col, weight) into one int2 so the hot loop does a single 8B load
// ---------------------------------------------------------------------------
__global__ void k_pack(const float* __restrict__ w, const int* __restrict__ cols, int nnz) {
    int i = blockIdx.x * 256 + threadIdx.x;
    if (i < nnz && i < MAXNNZ)
        g_packed[i] = make_int2(cols[i], __float_as_int(w[i]));
}

// ---------------------------------------------------------------------------
// 3) Segment pointers. COO is sorted by (row, col), so
//    key(i) = rows[i]*NTILE + (cols[i]>>CT_LOG) is non-decreasing.
//    g_seg[k] = first i with key(i) >= k  (binary search per k).
// ---------------------------------------------------------------------------
__global__ void k_seg(const int* __restrict__ rows, const int* __restrict__ cols, int nnz) {
    int k = blockIdx.x * 256 + threadIdx.x;
    if (k > NKEY) return;
    int lo = 0, hi = nnz;
    while (lo < hi) {
        int mid = (lo + hi) >> 1;
        int key = rows[mid] * NTILE + (cols[mid] >> CT_LOG);
        if (key >= k) hi = mid; else lo = mid + 1;
    }
    g_seg[k] = lo;
}

// ---------------------------------------------------------------------------
// 4) Main SpMM: CTA = (64 rows) x (256 batch). 8 warps; warp w owns rows
//    [rb*64 + w*8, +8). Lane covers batch b_local = lane*4..+3 and
//    128 + lane*4..+3 (two float4s, conflict-free LDS.128).
//    x tile (128 cols x 256 batch = 128 KB) staged in dynamic smem.
// ---------------------------------------------------------------------------
__global__ void k_spmm(const float* __restrict__ bias, float* __restrict__ y) {
    extern __shared__ float xs[];   // CT * BT floats = 128 KB

    const int rb   = blockIdx.x;          // row block (0..63)
    const int bt   = blockIdx.y;          // batch tile (0..31)
    const int tid  = threadIdx.x;
    const int warp = tid >> 5;
    const int lane = tid & 31;
    const int b_base = bt * BT;
    const int row0   = rb * RB + warp * 8;

    float acc[8][8];
#pragma unroll
    for (int r = 0; r < 8; r++)
#pragma unroll
        for (int j = 0; j < 8; j++) acc[r][j] = 0.0f;

    for (int t = 0; t < NTILE; t++) {
        __syncthreads();   // protect previous tile's readers
        const int c0 = t * CT;
        // Stage xT[c0:c0+128, b_base:b_base+256] into shared (float4, coalesced)
#pragma unroll
        for (int it = 0; it < (CT * BT / 4) / 256; it++) {   // 32 iters
            int idx = it * 256 + tid;
            int c_l = idx >> 6;            // 0..127
            int bq  = idx & 63;            // 0..63 (float4 slots)
            float4 v = *reinterpret_cast<const float4*>(
                &g_xT[(size_t)(c0 + c_l) * BATCH + b_base + bq * 4]);
            *reinterpret_cast<float4*>(&xs[c_l * BT + bq * 4]) = v;
        }
        __syncthreads();

#pragma unroll
        for (int r = 0; r < 8; r++) {
            const int row = row0 + r;
            const int kbase = row * NTILE + t;
            int s = g_seg[kbase];
            const int e = g_seg[kbase + 1];
            for (int i = s; i < e; i++) {
                const int2 p = g_packed[i];                 // broadcast 8B load
                const float w = __int_as_float(p.y);
                const float* base = &xs[(p.x - c0) * BT + lane * 4];
                const float4 v0 = *reinterpret_cast<const float4*>(base);
                const float4 v1 = *reinterpret_cast<const float4*>(base + 128);
                acc[r][0] = fmaf(w, v0.x, acc[r][0]);
                acc[r][1] = fmaf(w, v0.y, acc[r][1]);
                acc[r][2] = fmaf(w, v0.z, acc[r][2]);
                acc[r][3] = fmaf(w, v0.w, acc[r][3]);
                acc[r][4] = fmaf(w, v1.x, acc[r][4]);
                acc[r][5] = fmaf(w, v1.y, acc[r][5]);
                acc[r][6] = fmaf(w, v1.z, acc[r][6]);
                acc[r][7] = fmaf(w, v1.w, acc[r][7]);
            }
        }
    }

    // Epilogue: pack 4 consecutive rows into one float4 store -> each y segment
    // y[b, row0..row0+7] is a full 32B sector (2x STG.128 per b).
    const float4 bias_lo = *reinterpret_cast<const float4*>(&bias[row0]);
    const float4 bias_hi = *reinterpret_cast<const float4*>(&bias[row0 + 4]);
#pragma unroll
    for (int j = 0; j < 8; j++) {
        const int b = b_base + ((j < 4) ? (lane * 4 + j) : (128 + lane * 4 + (j - 4)));
        float4 lo, hi;
        lo.x = acc[0][j] + bias_lo.x;  lo.y = acc[1][j] + bias_lo.y;
        lo.z = acc[2][j] + bias_lo.z;  lo.w = acc[3][j] + bias_lo.w;
        hi.x = acc[4][j] + bias_hi.x;  hi.y = acc[5][j] + bias_hi.y;
        hi.z = acc[6][j] + bias_hi.z;  hi.w = acc[7][j] + bias_hi.w;
        *reinterpret_cast<float4*>(&y[(size_t)b * OUT_CH + row0])     = lo;
        *reinterpret_cast<float4*>(&y[(size_t)b * OUT_CH + row0 + 4]) = hi;
    }
}

// ---------------------------------------------------------------------------
// Launch (graph-capturable: kernel launches only, default stream)
// ---------------------------------------------------------------------------
extern "C" void kernel_launch(void* const* d_in, const int* in_sizes, int n_in,
                              void* d_out, int out_size) {
    const float* x     = (const float*)d_in[0];
    const float* w     = (const float*)d_in[1];
    const int*   rows  = (const int*)  d_in[2];
    const int*   cols  = (const int*)  d_in[3];
    const float* bias  = (const float*)d_in[4];
    float*       y     = (float*)d_out;
    const int    nnz   = in_sizes[1];

    // Opt in to 128 KB dynamic smem (idempotent, capture-safe host call)
    cudaFuncSetAttribute(k_spmm, cudaFuncAttributeMaxDynamicSharedMemorySize,
                         CT * BT * (int)sizeof(float));

    k_transpose<<<dim3(IN_CH / 32, BATCH / 32), dim3(32, 8)>>>(x);
    k_pack<<<(nnz + 255) / 256, 256>>>(w, cols, nnz);
    k_seg<<<(NKEY + 1 + 255) / 256, 256>>>(rows, cols, nnz);
    k_spmm<<<dim3(OUT_CH / RB, BATCH / BT), 256, CT * BT * (int)sizeof(float)>>>(bias, y);
}

// round 3
// speedup vs baseline: 1.5423x; 1.5423x over previous
#include <cuda_runtime.h>
#include <cstdint>

// Problem constants (fixed by the reference)
#define IN_CH   4096
#define OUT_CH  4096
#define BATCH   8192

// SpMM tiling
#define CT      64                  // columns (IN_CH) per shared tile (64 KB tile)
#define CT_LOG  6
#define NTILE   (IN_CH / CT)        // 64 column tiles
#define BT      256                 // batch per CTA
#define RB      32                  // output rows per CTA (16 warps x 2 rows)
#define NKEY    (OUT_CH * NTILE)    // 262144 segment keys
#define MAXNNZ  (1 << 21)           // 2M (actual ~1.68M)

// Scratch (device globals: allocation-free per harness rules)
__device__ float g_xT[(size_t)IN_CH * BATCH];   // 128 MB transposed x: xT[col][b]
__device__ int2  g_packed[MAXNNZ];              // (col, weight_bits) per nnz
__device__ int   g_seg[NKEY + 1];               // segment pointers per (row, ctile)

// ---------------------------------------------------------------------------
// 1) Transpose x [BATCH, IN_CH] -> g_xT [IN_CH, BATCH]
// ---------------------------------------------------------------------------
__global__ void k_transpose(const float* __restrict__ x) {
    __shared__ float tile[32][33];
    const int c0 = blockIdx.x * 32;
    const int b0 = blockIdx.y * 32;
    const int tx = threadIdx.x, ty = threadIdx.y;
#pragma unroll
    for (int j = 0; j < 4; j++)
        tile[ty + j * 8][tx] = x[(size_t)(b0 + ty + j * 8) * IN_CH + c0 + tx];
    __syncthreads();
#pragma unroll
    for (int j = 0; j < 4; j++)
        g_xT[(size_t)(c0 + ty + j * 8) * BATCH + b0 + tx] = tile[tx][ty + j * 8];
}

// ---------------------------------------------------------------------------
// 2) Pack (col, weight) into one int2 so the hot loop does a single 8B load
// ---------------------------------------------------------------------------
__global__ void k_pack(const float* __restrict__ w, const int* __restrict__ cols, int nnz) {
    int i = blockIdx.x * 256 + threadIdx.x;
    if (i < nnz && i < MAXNNZ)
        g_packed[i] = make_int2(cols[i], __float_as_int(w[i]));
}

// ---------------------------------------------------------------------------
// 3) Segment pointers. COO is (row, col)-sorted, so
//    key(i) = rows[i]*NTILE + (cols[i]>>CT_LOG) is non-decreasing.
//    g_seg[k] = first i with key(i) >= k.
// ---------------------------------------------------------------------------
__global__ void k_seg(const int* __restrict__ rows, const int* __restrict__ cols, int nnz) {
    int k = blockIdx.x * 256 + threadIdx.x;
    if (k > NKEY) return;
    int lo = 0, hi = nnz;
    while (lo < hi) {
        int mid = (lo + hi) >> 1;
        int key = rows[mid] * NTILE + (cols[mid] >> CT_LOG);
        if (key >= k) hi = mid; else lo = mid + 1;
    }
    g_seg[k] = lo;
}

// ---------------------------------------------------------------------------
// 4) Main SpMM: CTA = (32 rows) x (256 batch), 512 threads (16 warps).
//    Warp w owns rows [rb*32 + w*2, +2). Lane covers batch lane*4..+3 and
//    128+lane*4..+3 (two conflict-free LDS.128 per nnz).
//    x tile (64 cols x 256 batch = 64 KB) in dynamic smem -> 2 CTAs/SM.
// ---------------------------------------------------------------------------
__global__ void __launch_bounds__(512, 2)
k_spmm(const float* __restrict__ bias, float* __restrict__ y) {
    extern __shared__ float xs[];   // CT * BT floats = 64 KB

    const int rb    = blockIdx.x;         // row block (0..127)
    const int bt    = blockIdx.y;         // batch tile (0..31)
    const int tid   = threadIdx.x;
    const int warp  = tid >> 5;
    const int lane  = tid & 31;
    const int lane4 = lane * 4;
    const int b_base = bt * BT;
    const int row0   = rb * RB + warp * 2;

    float acc[2][8];
#pragma unroll
    for (int r = 0; r < 2; r++)
#pragma unroll
        for (int j = 0; j < 8; j++) acc[r][j] = 0.0f;

    for (int t = 0; t < NTILE; t++) {
        __syncthreads();   // protect previous tile's readers
        const int c0 = t * CT;
        // Stage xT[c0:c0+64, b_base:b_base+256] into shared (float4, coalesced)
#pragma unroll
        for (int it = 0; it < (CT * BT / 4) / 512; it++) {   // 8 iters
            int idx = it * 512 + tid;
            int c_l = idx >> 6;            // 0..63
            int bq  = idx & 63;            // float4 slot 0..63
            float4 v = *reinterpret_cast<const float4*>(
                &g_xT[(size_t)(c0 + c_l) * BATCH + b_base + bq * 4]);
            *reinterpret_cast<float4*>(&xs[c_l * BT + bq * 4]) = v;
        }
        __syncthreads();

        const int off0 = lane4 - c0 * BT;  // so smem idx = col*BT + off0 (1 IMAD)
#pragma unroll
        for (int r = 0; r < 2; r++) {
            const int kbase = (row0 + r) * NTILE + t;
            const int s = g_seg[kbase];
            const int e = g_seg[kbase + 1];
#pragma unroll 2
            for (int i = s; i < e; i++) {
                const int2 p = g_packed[i];                 // broadcast 8B load
                const float w = __int_as_float(p.y);
                const float* base = &xs[p.x * BT + off0];
                const float4 v0 = *reinterpret_cast<const float4*>(base);
                const float4 v1 = *reinterpret_cast<const float4*>(base + 128);
                acc[r][0] = fmaf(w, v0.x, acc[r][0]);
                acc[r][1] = fmaf(w, v0.y, acc[r][1]);
                acc[r][2] = fmaf(w, v0.z, acc[r][2]);
                acc[r][3] = fmaf(w, v0.w, acc[r][3]);
                acc[r][4] = fmaf(w, v1.x, acc[r][4]);
                acc[r][5] = fmaf(w, v1.y, acc[r][5]);
                acc[r][6] = fmaf(w, v1.z, acc[r][6]);
                acc[r][7] = fmaf(w, v1.w, acc[r][7]);
            }
        }
    }

    // Epilogue: 2 consecutive rows per warp -> float2 stores (8B aligned).
    const float2 bw = *reinterpret_cast<const float2*>(&bias[row0]);
#pragma unroll
    for (int j = 0; j < 8; j++) {
        const int b = b_base + ((j < 4) ? (lane4 + j) : (128 + lane4 + (j - 4)));
        float2 v;
        v.x = acc[0][j] + bw.x;
        v.y = acc[1][j] + bw.y;
        *reinterpret_cast<float2*>(&y[(size_t)b * OUT_CH + row0]) = v;
    }
}

// ---------------------------------------------------------------------------
// Launch (graph-capturable: kernel launches only, default stream)
// ---------------------------------------------------------------------------
extern "C" void kernel_launch(void* const* d_in, const int* in_sizes, int n_in,
                              void* d_out, int out_size) {
    const float* x     = (const float*)d_in[0];
    const float* w     = (const float*)d_in[1];
    const int*   rows  = (const int*)  d_in[2];
    const int*   cols  = (const int*)  d_in[3];
    const float* bias  = (const float*)d_in[4];
    float*       y     = (float*)d_out;
    const int    nnz   = in_sizes[1];

    cudaFuncSetAttribute(k_spmm, cudaFuncAttributeMaxDynamicSharedMemorySize,
                         CT * BT * (int)sizeof(float));

    k_transpose<<<dim3(IN_CH / 32, BATCH / 32), dim3(32, 8)>>>(x);
    k_pack<<<(nnz + 255) / 256, 256>>>(w, cols, nnz);
    k_seg<<<(NKEY + 1 + 255) / 256, 256>>>(rows, cols, nnz);
    k_spmm<<<dim3(OUT_CH / RB, BATCH / BT), 512, CT * BT * (int)sizeof(float)>>>(bias, y);
}

// round 6
// speedup vs baseline: 2.8644x; 1.8572x over previous
#include <cuda_runtime.h>
#include <cuda_bf16.h>
#include <cstdint>

// Problem constants
#define IN_CH   4096
#define OUT_CH  4096
#define BATCH   8192

// GEMM tiling
#define TM      128                  // batch rows per CTA tile
#define TN      256                  // out_ch cols per CTA tile
#define KC      64                   // K per chunk (64 bf16 = 128 B = SW128 row)
#define NCHUNK  (IN_CH / KC)         // 64
#define NTHREADS 256                 // 8 warps, warp grid 2(m) x 4(n), warp tile 64x64

// smem: 2 stages of [Ahi|Alo|Bhi|Blo]
#define A_BYTES     (TM * 128)                     // 16384
#define B_BYTES     (TN * 128)                     // 32768
#define STAGE_BYTES (2 * A_BYTES + 2 * B_BYTES)    // 98304
#define SMEM_TOTAL  (2 * STAGE_BYTES)              // 196608

// SW128 swizzle
#define SWZ(o) ((o) ^ (((o) >> 3) & 0x70))

// Scratch (device globals: allocation-free per harness rules) — 192 MB
__device__ __nv_bfloat16 g_xhi[(size_t)BATCH * IN_CH];
__device__ __nv_bfloat16 g_xlo[(size_t)BATCH * IN_CH];
__device__ __nv_bfloat16 g_whi[(size_t)OUT_CH * IN_CH];
__device__ __nv_bfloat16 g_wlo[(size_t)OUT_CH * IN_CH];

// ---------------------------------------------------------------------------
// PTX helpers (all baseline sm_80+ instructions — valid on plain sm_103 target)
// ---------------------------------------------------------------------------
__device__ __forceinline__ uint32_t smem_u32(const void* p) {
    uint32_t a;
    asm("{ .reg .u64 t; cvta.to.shared.u64 t, %1; cvt.u32.u64 %0, t; }"
        : "=r"(a) : "l"(p));
    return a;
}
__device__ __forceinline__ void ldsm4(uint32_t* r, uint32_t addr) {
    asm volatile("ldmatrix.sync.aligned.m8n8.x4.shared.b16 {%0,%1,%2,%3}, [%4];"
                 : "=r"(r[0]), "=r"(r[1]), "=r"(r[2]), "=r"(r[3]) : "r"(addr));
}
__device__ __forceinline__ void mma_bf16(float* d, const uint32_t* a, const uint32_t* b) {
    asm volatile(
        "mma.sync.aligned.m16n8k16.row.col.f32.bf16.bf16.f32 "
        "{%0,%1,%2,%3}, {%4,%5,%6,%7}, {%8,%9}, {%0,%1,%2,%3};"
        : "+f"(d[0]), "+f"(d[1]), "+f"(d[2]), "+f"(d[3])
        : "r"(a[0]), "r"(a[1]), "r"(a[2]), "r"(a[3]), "r"(b[0]), "r"(b[1]));
}

// ---------------------------------------------------------------------------
// Prep kernels: fp32 -> bf16 hi + bf16 residual
// ---------------------------------------------------------------------------
__global__ void k_cvt_x(const float* __restrict__ x) {
    size_t i = ((size_t)blockIdx.x * 256 + threadIdx.x) * 4;
    float4 v = *reinterpret_cast<const float4*>(&x[i]);
    __nv_bfloat16 h0 = __float2bfloat16(v.x), h1 = __float2bfloat16(v.y);
    __nv_bfloat16 h2 = __float2bfloat16(v.z), h3 = __float2bfloat16(v.w);
    __nv_bfloat162* ph = reinterpret_cast<__nv_bfloat162*>(&g_xhi[i]);
    __nv_bfloat162* pl = reinterpret_cast<__nv_bfloat162*>(&g_xlo[i]);
    ph[0] = __nv_bfloat162(h0, h1);
    ph[1] = __nv_bfloat162(h2, h3);
    pl[0] = __nv_bfloat162(__float2bfloat16(v.x - __bfloat162float(h0)),
                           __float2bfloat16(v.y - __bfloat162float(h1)));
    pl[1] = __nv_bfloat162(__float2bfloat16(v.z - __bfloat162float(h2)),
                           __float2bfloat16(v.w - __bfloat162float(h3)));
}

__global__ void k_zero_w() {
    size_t i = ((size_t)blockIdx.x * 256 + threadIdx.x) * 8;   // 8 bf16 = 16 B
    uint4 z = make_uint4(0, 0, 0, 0);
    *reinterpret_cast<uint4*>(&g_whi[i]) = z;
    *reinterpret_cast<uint4*>(&g_wlo[i]) = z;
}

__global__ void k_scatter_w(const float* __restrict__ w, const int* __restrict__ rows,
                            const int* __restrict__ cols, int nnz) {
    int i = blockIdx.x * 256 + threadIdx.x;
    if (i >= nnz) return;
    float v = w[i];
    __nv_bfloat16 h = __float2bfloat16(v);
    size_t o = (size_t)rows[i] * IN_CH + cols[i];
    g_whi[o] = h;
    g_wlo[o] = __float2bfloat16(v - __bfloat162float(h));
}

// ---------------------------------------------------------------------------
// cp.async loader: one k-chunk (Ahi|Alo|Bhi|Blo) into a stage, SW128 swizzled
// ---------------------------------------------------------------------------
__device__ __forceinline__ void load_chunk(uint32_t sbase, int chunk, int stage,
                                           int m0, int n0, int tid) {
    const int k0 = chunk * KC;
    const uint32_t stbase = sbase + stage * STAGE_BYTES;
#pragma unroll
    for (int j = tid; j < 6144; j += NTHREADS) {
        const __nv_bfloat16* src;
        uint32_t dst;
        if (j < 2048) {                       // A: 2 bufs x 128 rows x 8 x 16B
            int buf = j >> 10, idx = j & 1023;
            int r = idx >> 3, c16 = idx & 7;
            const __nv_bfloat16* g = buf ? g_xlo : g_xhi;
            src = g + (size_t)(m0 + r) * IN_CH + k0 + c16 * 8;
            dst = stbase + buf * A_BYTES + SWZ((uint32_t)(r * 128 + c16 * 16));
        } else {                              // B: 2 bufs x 256 rows x 8 x 16B
            int jb = j - 2048;
            int buf = jb >> 11, idx = jb & 2047;
            int r = idx >> 3, c16 = idx & 7;
            const __nv_bfloat16* g = buf ? g_wlo : g_whi;
            src = g + (size_t)(n0 + r) * IN_CH + k0 + c16 * 8;
            dst = stbase + 2 * A_BYTES + buf * B_BYTES
                + SWZ((uint32_t)(r * 128 + c16 * 16));
        }
        asm volatile("cp.async.cg.shared.global [%0], [%1], 16;" :: "r"(dst), "l"(src));
    }
    asm volatile("cp.async.commit_group;" ::: "memory");
}

// ---------------------------------------------------------------------------
// Main GEMM: y[128 x 256] = xhi*Whi + xhi*Wlo + xlo*Whi (+bias), mma.sync bf16
// ---------------------------------------------------------------------------
__global__ void __launch_bounds__(NTHREADS)
k_gemm(const float* __restrict__ bias, float* __restrict__ y) {
    extern __shared__ char smem[];
    const uint32_t sbase = smem_u32(smem);
    const int tid  = threadIdx.x;
    const int warp = tid >> 5;
    const int lane = tid & 31;
    const int wm   = warp >> 2;           // 0..1  (m)
    const int wn   = warp & 3;            // 0..3  (n)
    const int n0   = blockIdx.x * TN;     // x fastest -> B slices shared per wave
    const int m0   = blockIdx.y * TM;

    // ldmatrix per-thread row offsets (bytes into tile) + swizzle mask.
    // A tiles: groups of 8 lanes -> (m0-7,k0),(m8-15,k0),(m0-7,k+16),(m8-15,k+16)
    const uint32_t amask = (uint32_t)(lane & 7) << 4;
    uint32_t arow[4];
#pragma unroll
    for (int mt = 0; mt < 4; mt++)
        arow[mt] = (uint32_t)((wm * 64 + mt * 16 + (lane & 15)) * 128
                              + ((lane >> 4) & 1) * 16);
    // B tiles: groups -> (n0-7,k0),(n0-7,k+16),(n8-15,k0),(n8-15,k+16)
    uint32_t brow[4];
#pragma unroll
    for (int nt = 0; nt < 4; nt++)
        brow[nt] = (uint32_t)((wn * 64 + nt * 16 + (lane & 7) + ((lane >> 4) & 1) * 8) * 128
                              + ((lane >> 3) & 1) * 16);

    float acc[4][8][4];
#pragma unroll
    for (int mt = 0; mt < 4; mt++)
#pragma unroll
        for (int n8 = 0; n8 < 8; n8++)
#pragma unroll
            for (int q = 0; q < 4; q++) acc[mt][n8][q] = 0.0f;

    // Prologue: prefetch chunks 0, 1
    load_chunk(sbase, 0, 0, m0, n0, tid);
    load_chunk(sbase, 1, 1, m0, n0, tid);

    for (int i = 0; i < NCHUNK; i++) {
        if (i + 2 < NCHUNK)
            asm volatile("cp.async.wait_group 1;" ::: "memory");
        else
            asm volatile("cp.async.wait_group 0;" ::: "memory");
        __syncthreads();

        const int st = i & 1;
        const uint32_t stb   = sbase + st * STAGE_BYTES;
        const uint32_t Ahi_b = stb;
        const uint32_t Alo_b = stb + A_BYTES;
        const uint32_t Bhi_b = stb + 2 * A_BYTES;
        const uint32_t Blo_b = Bhi_b + B_BYTES;

#pragma unroll
        for (int kt = 0; kt < 4; kt++) {
            const uint32_t kb = (uint32_t)(kt * 32);
            uint32_t ahi[4][4], alo[4][4], bb[4][4];
#pragma unroll
            for (int mt = 0; mt < 4; mt++) {
                const uint32_t so = (arow[mt] + kb) ^ amask;
                ldsm4(ahi[mt], Ahi_b + so);
                ldsm4(alo[mt], Alo_b + so);
            }
#pragma unroll
            for (int nt = 0; nt < 4; nt++)
                ldsm4(bb[nt], Bhi_b + ((brow[nt] + kb) ^ amask));
#pragma unroll
            for (int mt = 0; mt < 4; mt++)
#pragma unroll
                for (int nt = 0; nt < 4; nt++) {
                    mma_bf16(acc[mt][nt * 2],     ahi[mt], &bb[nt][0]);
                    mma_bf16(acc[mt][nt * 2 + 1], ahi[mt], &bb[nt][2]);
                    mma_bf16(acc[mt][nt * 2],     alo[mt], &bb[nt][0]);
                    mma_bf16(acc[mt][nt * 2 + 1], alo[mt], &bb[nt][2]);
                }
#pragma unroll
            for (int nt = 0; nt < 4; nt++)
                ldsm4(bb[nt], Blo_b + ((brow[nt] + kb) ^ amask));
#pragma unroll
            for (int mt = 0; mt < 4; mt++)
#pragma unroll
                for (int nt = 0; nt < 4; nt++) {
                    mma_bf16(acc[mt][nt * 2],     ahi[mt], &bb[nt][0]);
                    mma_bf16(acc[mt][nt * 2 + 1], ahi[mt], &bb[nt][2]);
                }
        }

        __syncthreads();   // all warps done reading this stage
        if (i + 2 < NCHUNK)
            load_chunk(sbase, i + 2, st, m0, n0, tid);
    }

    // Epilogue: acc layout per mma: c0,c1=(m + l/4, n + 2(l%4)+{0,1}), c2,c3=(m+8, ...)
    const int mw = m0 + wm * 64 + (lane >> 2);
    const int nw = n0 + wn * 64 + 2 * (lane & 3);
#pragma unroll
    for (int mt = 0; mt < 4; mt++) {
        const size_t r0 = (size_t)(mw + mt * 16) * OUT_CH;
        const size_t r1 = r0 + 8 * OUT_CH;
#pragma unroll
        for (int n8 = 0; n8 < 8; n8++) {
            const int n = nw + n8 * 8;
            const float2 bv = *reinterpret_cast<const float2*>(&bias[n]);
            float2 v0, v1;
            v0.x = acc[mt][n8][0] + bv.x;  v0.y = acc[mt][n8][1] + bv.y;
            v1.x = acc[mt][n8][2] + bv.x;  v1.y = acc[mt][n8][3] + bv.y;
            *reinterpret_cast<float2*>(&y[r0 + n]) = v0;
            *reinterpret_cast<float2*>(&y[r1 + n]) = v1;
        }
    }
}

// ---------------------------------------------------------------------------
// Launch (graph-capturable: kernel launches only, default stream)
// ---------------------------------------------------------------------------
extern "C" void kernel_launch(void* const* d_in, const int* in_sizes, int n_in,
                              void* d_out, int out_size) {
    const float* x    = (const float*)d_in[0];
    const float* w    = (const float*)d_in[1];
    const int*   rows = (const int*)  d_in[2];
    const int*   cols = (const int*)  d_in[3];
    const float* bias = (const float*)d_in[4];
    float*       y    = (float*)d_out;
    const int    nnz  = in_sizes[1];

    cudaFuncSetAttribute(k_gemm, cudaFuncAttributeMaxDynamicSharedMemorySize,
                         SMEM_TOTAL);

    k_cvt_x<<<(BATCH * IN_CH / 4) / 256, 256>>>(x);
    k_zero_w<<<(int)(((size_t)OUT_CH * IN_CH / 8) / 256), 256>>>();
    k_scatter_w<<<(nnz + 255) / 256, 256>>>(w, rows, cols, nnz);
    k_gemm<<<dim3(OUT_CH / TN, BATCH / TM), NTHREADS, SMEM_TOTAL>>>(bias, y);
}

// round 7
// speedup vs baseline: 3.6841x; 1.2862x over previous
#include <cuda_runtime.h>
#include <cuda_bf16.h>
#include <cstdint>

// Problem constants
#define IN_CH   4096
#define OUT_CH  4096
#define BATCH   8192

// GEMM tiling (tf32: 4 B/elem)
#define TM      128                  // batch rows per CTA tile
#define TN      256                  // out_ch cols per CTA tile
#define KC      32                   // K per chunk (32 tf32 = 128 B = swizzle row)
#define NCHUNK  (IN_CH / KC)         // 128
#define NSTAGE  4
#define NTHREADS 256                 // 8 warps, warp grid 2(m) x 4(n), warp tile 64x64

// smem: 4 stages of [A|B], fp32/tf32 elements
#define A_BYTES     (TM * 128)                     // 16384
#define B_BYTES     (TN * 128)                     // 32768
#define STAGE_BYTES (A_BYTES + B_BYTES)            // 49152
#define SMEM_TOTAL  (NSTAGE * STAGE_BYTES)         // 196608

// Scratch (device globals: allocation-free per harness rules) — 192 MB
__device__ uint32_t g_x32[(size_t)BATCH * IN_CH];   // tf32-rounded x
__device__ uint32_t g_w32[(size_t)OUT_CH * IN_CH];  // tf32-rounded dense W

// ---------------------------------------------------------------------------
// PTX helpers (baseline sm_80+ instructions — valid on plain sm_103 target)
// ---------------------------------------------------------------------------
__device__ __forceinline__ uint32_t smem_u32(const void* p) {
    uint32_t a;
    asm("{ .reg .u64 t; cvta.to.shared.u64 t, %1; cvt.u32.u64 %0, t; }"
        : "=r"(a) : "l"(p));
    return a;
}
__device__ __forceinline__ uint32_t to_tf32(float v) {
    uint32_t r;
    asm("cvt.rna.tf32.f32 %0, %1;" : "=r"(r) : "f"(v));
    return r;
}
__device__ __forceinline__ void ldsm4(uint32_t* r, uint32_t addr) {
    asm volatile("ldmatrix.sync.aligned.m8n8.x4.shared.b16 {%0,%1,%2,%3}, [%4];"
                 : "=r"(r[0]), "=r"(r[1]), "=r"(r[2]), "=r"(r[3]) : "r"(addr));
}
__device__ __forceinline__ void mma_tf32(float* d, const uint32_t* a, const uint32_t* b) {
    asm volatile(
        "mma.sync.aligned.m16n8k8.row.col.f32.tf32.tf32.f32 "
        "{%0,%1,%2,%3}, {%4,%5,%6,%7}, {%8,%9}, {%0,%1,%2,%3};"
        : "+f"(d[0]), "+f"(d[1]), "+f"(d[2]), "+f"(d[3])
        : "r"(a[0]), "r"(a[1]), "r"(a[2]), "r"(a[3]), "r"(b[0]), "r"(b[1]));
}

// ---------------------------------------------------------------------------
// Prep kernels: fp32 -> tf32-rounded fp32 (rna)
// ---------------------------------------------------------------------------
__global__ void k_cvt_x(const float* __restrict__ x) {
    size_t i = ((size_t)blockIdx.x * 256 + threadIdx.x) * 4;
    float4 v = *reinterpret_cast<const float4*>(&x[i]);
    uint4 o;
    o.x = to_tf32(v.x); o.y = to_tf32(v.y);
    o.z = to_tf32(v.z); o.w = to_tf32(v.w);
    *reinterpret_cast<uint4*>(&g_x32[i]) = o;
}

__global__ void k_zero_w() {
    size_t i = ((size_t)blockIdx.x * 256 + threadIdx.x) * 4;
    *reinterpret_cast<uint4*>(&g_w32[i]) = make_uint4(0, 0, 0, 0);
}

__global__ void k_scatter_w(const float* __restrict__ w, const int* __restrict__ rows,
                            const int* __restrict__ cols, int nnz) {
    int i = blockIdx.x * 256 + threadIdx.x;
    if (i >= nnz) return;
    g_w32[(size_t)rows[i] * IN_CH + cols[i]] = to_tf32(w[i]);
}

// ---------------------------------------------------------------------------
// cp.async loader: one k-chunk (A 128x32 | B 256x32 tf32) into a stage.
// Swizzle: 16B segment s of row r stored at segment (s ^ (r & 7)).
// ---------------------------------------------------------------------------
__device__ __forceinline__ void load_chunk(uint32_t sbase, int chunk, int stage,
                                           int m0, int n0, int tid) {
    const int k0 = chunk * KC;
    const uint32_t stA = sbase + stage * STAGE_BYTES;
    const uint32_t stB = stA + A_BYTES;
#pragma unroll
    for (int it = 0; it < 3072 / NTHREADS; it++) {   // 12 iters of 16B
        int j = it * NTHREADS + tid;
        const uint32_t* src;
        uint32_t dst;
        if (j < 1024) {                       // A: 128 rows x 8 segs
            int r = j >> 3, s = j & 7;
            src = g_x32 + (size_t)(m0 + r) * IN_CH + k0 + s * 4;
            dst = stA + (uint32_t)(r * 128 + ((s ^ (r & 7)) * 16));
        } else {                              // B: 256 rows x 8 segs
            int jb = j - 1024;
            int r = jb >> 3, s = jb & 7;
            src = g_w32 + (size_t)(n0 + r) * IN_CH + k0 + s * 4;
            dst = stB + (uint32_t)(r * 128 + ((s ^ (r & 7)) * 16));
        }
        asm volatile("cp.async.cg.shared.global [%0], [%1], 16;" :: "r"(dst), "l"(src));
    }
    asm volatile("cp.async.commit_group;" ::: "memory");
}

// ---------------------------------------------------------------------------
// Main GEMM: y[128 x 256] = x @ W^T + bias, single-pass tf32 mma.sync
// ---------------------------------------------------------------------------
__global__ void __launch_bounds__(NTHREADS)
k_gemm(const float* __restrict__ bias, float* __restrict__ y) {
    extern __shared__ char smem[];
    const uint32_t sbase = smem_u32(smem);
    const int tid  = threadIdx.x;
    const int warp = tid >> 5;
    const int lane = tid & 31;
    const int wm   = warp >> 2;           // 0..1  (m)
    const int wn   = warp & 3;            // 0..3  (n)
    const int n0   = blockIdx.x * TN;     // x fastest -> W tiles shared per wave
    const int m0   = blockIdx.y * TM;

    // ldmatrix addresses (tf32 fragments via b16 ldmatrix: 8x8 b16 tile == 8x4
    // tf32 tile; lane l gets (row l/4, word l%4) = exact tf32 frag layout).
    // A x4 tiles for (mt, kt): g=l>>3 -> {m+0-7,ks0},{m+8-15,ks0},{m+0-7,ks1},{m+8-15,ks1}
    const int l7   = lane & 7;
    const int amr  = wm * 64 + l7 + ((lane >> 3) & 1) * 8;   // m row within frag
    const int akl  = lane >> 4;                              // kseg low bit
    // B x4 tiles for (j, kt): g -> {n+0-7,ks0},{n+0-7,ks1},{n+8-15,ks0},{n+8-15,ks1}
    const int bnr  = wn * 64 + l7 + (lane >> 4) * 8;         // n row within frag
    const int bkl  = (lane >> 3) & 1;

    float acc[4][8][4];
#pragma unroll
    for (int mt = 0; mt < 4; mt++)
#pragma unroll
        for (int n8 = 0; n8 < 8; n8++)
#pragma unroll
            for (int q = 0; q < 4; q++) acc[mt][n8][q] = 0.0f;

    // Prologue: prefetch chunks 0..2
    load_chunk(sbase, 0, 0, m0, n0, tid);
    load_chunk(sbase, 1, 1, m0, n0, tid);
    load_chunk(sbase, 2, 2, m0, n0, tid);

    for (int i = 0; i < NCHUNK; i++) {
        if (i < NCHUNK - 2)
            asm volatile("cp.async.wait_group 2;" ::: "memory");
        else
            asm volatile("cp.async.wait_group 0;" ::: "memory");
        __syncthreads();   // chunk i visible to all; stage (i-1)&3 fully consumed

        if (i + 3 < NCHUNK)
            load_chunk(sbase, i + 3, (i + 3) & NSTAGE - 1, m0, n0, tid);

        const uint32_t stA = sbase + (i & (NSTAGE - 1)) * STAGE_BYTES;
        const uint32_t stB = stA + A_BYTES;

#pragma unroll
        for (int kt = 0; kt < 4; kt++) {
            uint32_t a[4][4], b[4][4];
#pragma unroll
            for (int mt = 0; mt < 4; mt++) {
                const int mr = amr + mt * 16;
                const int ks = kt * 2 + akl;
                ldsm4(a[mt], stA + mr * 128 + ((ks ^ l7) * 16));
            }
#pragma unroll
            for (int j = 0; j < 4; j++) {
                const int nr = bnr + j * 16;
                const int ks = kt * 2 + bkl;
                ldsm4(b[j], stB + nr * 128 + ((ks ^ l7) * 16));
            }
#pragma unroll
            for (int mt = 0; mt < 4; mt++)
#pragma unroll
                for (int j = 0; j < 4; j++) {
                    mma_tf32(acc[mt][j * 2],     a[mt], &b[j][0]);
                    mma_tf32(acc[mt][j * 2 + 1], a[mt], &b[j][2]);
                }
        }
    }

    // Epilogue: c0,c1=(m + l/4, n + 2(l%4)+{0,1}), c2,c3=(m+8, ...)
    const int mw = m0 + wm * 64 + (lane >> 2);
    const int nw = n0 + wn * 64 + 2 * (lane & 3);
#pragma unroll
    for (int mt = 0; mt < 4; mt++) {
        const size_t r0 = (size_t)(mw + mt * 16) * OUT_CH;
        const size_t r1 = r0 + 8 * OUT_CH;
#pragma unroll
        for (int n8 = 0; n8 < 8; n8++) {
            const int n = nw + n8 * 8;
            const float2 bv = *reinterpret_cast<const float2*>(&bias[n]);
            float2 v0, v1;
            v0.x = acc[mt][n8][0] + bv.x;  v0.y = acc[mt][n8][1] + bv.y;
            v1.x = acc[mt][n8][2] + bv.x;  v1.y = acc[mt][n8][3] + bv.y;
            *reinterpret_cast<float2*>(&y[r0 + n]) = v0;
            *reinterpret_cast<float2*>(&y[r1 + n]) = v1;
        }
    }
}

// ---------------------------------------------------------------------------
// Launch (graph-capturable: kernel launches only, default stream)
// ---------------------------------------------------------------------------
extern "C" void kernel_launch(void* const* d_in, const int* in_sizes, int n_in,
                              void* d_out, int out_size) {
    const float* x    = (const float*)d_in[0];
    const float* w    = (const float*)d_in[1];
    const int*   rows = (const int*)  d_in[2];
    const int*   cols = (const int*)  d_in[3];
    const float* bias = (const float*)d_in[4];
    float*       y    = (float*)d_out;
    const int    nnz  = in_sizes[1];

    cudaFuncSetAttribute(k_gemm, cudaFuncAttributeMaxDynamicSharedMemorySize,
                         SMEM_TOTAL);

    k_cvt_x<<<(BATCH * IN_CH / 4) / 256, 256>>>(x);
    k_zero_w<<<(int)(((size_t)OUT_CH * IN_CH / 4) / 256), 256>>>();
    k_scatter_w<<<(nnz + 255) / 256, 256>>>(w, rows, cols, nnz);
    k_gemm<<<dim3(OUT_CH / TN, BATCH / TM), NTHREADS, SMEM_TOTAL>>>(bias, y);
}

// round 8
// speedup vs baseline: 4.0851x; 1.1089x over previous
#include <cuda_runtime.h>
#include <cuda_bf16.h>
#include <cstdint>

// Problem constants
#define IN_CH   4096
#define OUT_CH  4096
#define BATCH   8192

// GEMM tiling (tf32: 4 B/elem)
#define TM      128                  // batch rows per CTA tile
#define TN      128                  // out_ch cols per CTA tile
#define KC      32                   // K per chunk (32 tf32 = 128 B = swizzle row)
#define NCHUNK  (IN_CH / KC)         // 128
#define NSTAGE  3
#define NTHREADS 256                 // 8 warps, warp grid 2(m) x 4(n), warp tile 64x32

// smem: 3 stages of [A|B]
#define A_BYTES     (TM * 128)                     // 16384
#define B_BYTES     (TN * 128)                     // 16384
#define STAGE_BYTES (A_BYTES + B_BYTES)            // 32768
#define SMEM_TOTAL  (NSTAGE * STAGE_BYTES)         // 98304 -> 2 CTAs/SM

// Scratch (device globals: allocation-free per harness rules) — 192 MB
__device__ uint32_t g_x32[(size_t)BATCH * IN_CH];   // tf32-rounded x
__device__ uint32_t g_w32[(size_t)OUT_CH * IN_CH];  // tf32-rounded dense W

// ---------------------------------------------------------------------------
// PTX helpers (baseline sm_80+ instructions — valid on plain sm_103 target)
// ---------------------------------------------------------------------------
__device__ __forceinline__ uint32_t smem_u32(const void* p) {
    uint32_t a;
    asm("{ .reg .u64 t; cvta.to.shared.u64 t, %1; cvt.u32.u64 %0, t; }"
        : "=r"(a) : "l"(p));
    return a;
}
__device__ __forceinline__ uint32_t to_tf32(float v) {
    uint32_t r;
    asm("cvt.rna.tf32.f32 %0, %1;" : "=r"(r) : "f"(v));
    return r;
}
__device__ __forceinline__ void ldsm4(uint32_t* r, uint32_t addr) {
    asm volatile("ldmatrix.sync.aligned.m8n8.x4.shared.b16 {%0,%1,%2,%3}, [%4];"
                 : "=r"(r[0]), "=r"(r[1]), "=r"(r[2]), "=r"(r[3]) : "r"(addr));
}
__device__ __forceinline__ void mma_tf32(float* d, const uint32_t* a, const uint32_t* b) {
    asm volatile(
        "mma.sync.aligned.m16n8k8.row.col.f32.tf32.tf32.f32 "
        "{%0,%1,%2,%3}, {%4,%5,%6,%7}, {%8,%9}, {%0,%1,%2,%3};"
        : "+f"(d[0]), "+f"(d[1]), "+f"(d[2]), "+f"(d[3])
        : "r"(a[0]), "r"(a[1]), "r"(a[2]), "r"(a[3]), "r"(b[0]), "r"(b[1]));
}

// ---------------------------------------------------------------------------
// Prep kernels: fp32 -> tf32-rounded fp32 (rna)
// ---------------------------------------------------------------------------
__global__ void k_cvt_x(const float* __restrict__ x) {
    size_t i = ((size_t)blockIdx.x * 256 + threadIdx.x) * 4;
    float4 v = *reinterpret_cast<const float4*>(&x[i]);
    uint4 o;
    o.x = to_tf32(v.x); o.y = to_tf32(v.y);
    o.z = to_tf32(v.z); o.w = to_tf32(v.w);
    *reinterpret_cast<uint4*>(&g_x32[i]) = o;
}

__global__ void k_zero_w() {
    size_t i = ((size_t)blockIdx.x * 256 + threadIdx.x) * 4;
    *reinterpret_cast<uint4*>(&g_w32[i]) = make_uint4(0, 0, 0, 0);
}

__global__ void k_scatter_w(const float* __restrict__ w, const int* __restrict__ rows,
                            const int* __restrict__ cols, int nnz) {
    int i = blockIdx.x * 256 + threadIdx.x;
    if (i >= nnz) return;
    g_w32[(size_t)rows[i] * IN_CH + cols[i]] = to_tf32(w[i]);
}

// ---------------------------------------------------------------------------
// cp.async loader: one k-chunk (A 128x32 | B 128x32 tf32) into a stage.
// Swizzle: 16B segment s of row r stored at segment (s ^ (r & 7)).
// ---------------------------------------------------------------------------
__device__ __forceinline__ void load_chunk(uint32_t sbase, int chunk, int stage,
                                           int m0, int n0, int tid) {
    const int k0 = chunk * KC;
    const uint32_t stA = sbase + stage * STAGE_BYTES;
    const uint32_t stB = stA + A_BYTES;
#pragma unroll
    for (int it = 0; it < 2048 / NTHREADS; it++) {   // 8 iters of 16B
        int j = it * NTHREADS + tid;
        const uint32_t* src;
        uint32_t dst;
        if (j < 1024) {                       // A: 128 rows x 8 segs
            int r = j >> 3, s = j & 7;
            src = g_x32 + (size_t)(m0 + r) * IN_CH + k0 + s * 4;
            dst = stA + (uint32_t)(r * 128 + ((s ^ (r & 7)) * 16));
        } else {                              // B: 128 rows x 8 segs
            int jb = j - 1024;
            int r = jb >> 3, s = jb & 7;
            src = g_w32 + (size_t)(n0 + r) * IN_CH + k0 + s * 4;
            dst = stB + (uint32_t)(r * 128 + ((s ^ (r & 7)) * 16));
        }
        asm volatile("cp.async.cg.shared.global [%0], [%1], 16;" :: "r"(dst), "l"(src));
    }
    asm volatile("cp.async.commit_group;" ::: "memory");
}

// ---------------------------------------------------------------------------
// Main GEMM: y[128 x 128] = x @ W^T + bias, single-pass tf32 mma.sync
// ---------------------------------------------------------------------------
__global__ void __launch_bounds__(NTHREADS, 2)
k_gemm(const float* __restrict__ bias, float* __restrict__ y) {
    extern __shared__ char smem[];
    const uint32_t sbase = smem_u32(smem);
    const int tid  = threadIdx.x;
    const int warp = tid >> 5;
    const int lane = tid & 31;
    const int wm   = warp >> 2;           // 0..1  (m)
    const int wn   = warp & 3;            // 0..3  (n)
    const int n0   = blockIdx.x * TN;     // x fastest -> W tiles shared per wave
    const int m0   = blockIdx.y * TM;

    // ldmatrix addresses (tf32 frags via b16 ldmatrix: 8x8 b16 == 8x4 tf32;
    // lane l gets (row l/4, word l%4) = exact tf32 fragment layout).
    const int l7   = lane & 7;
    const int amr  = wm * 64 + l7 + ((lane >> 3) & 1) * 8;   // A: m row in frag
    const int akl  = lane >> 4;                              // A: kseg low bit
    const int bnr  = wn * 32 + l7 + (lane >> 4) * 8;         // B: n row in frag
    const int bkl  = (lane >> 3) & 1;                        // B: kseg low bit

    float acc[4][4][4];
#pragma unroll
    for (int mt = 0; mt < 4; mt++)
#pragma unroll
        for (int n8 = 0; n8 < 4; n8++)
#pragma unroll
            for (int q = 0; q < 4; q++) acc[mt][n8][q] = 0.0f;

    // Prologue: prefetch chunks 0, 1 (stages 0, 1)
    load_chunk(sbase, 0, 0, m0, n0, tid);
    load_chunk(sbase, 1, 1, m0, n0, tid);

    for (int i = 0; i < NCHUNK; i++) {
        if (i < NCHUNK - 1)
            asm volatile("cp.async.wait_group 1;" ::: "memory");
        else
            asm volatile("cp.async.wait_group 0;" ::: "memory");
        __syncthreads();   // chunk i visible; stage (i+2)%3's old chunk consumed

        if (i + 2 < NCHUNK) {
            int st_next = i + 2;
            load_chunk(sbase, st_next, st_next % NSTAGE, m0, n0, tid);
        }

        const uint32_t stA = sbase + (i % NSTAGE) * STAGE_BYTES;
        const uint32_t stB = stA + A_BYTES;

#pragma unroll
        for (int kt = 0; kt < 4; kt++) {
            uint32_t a[4][4], b[2][4];
#pragma unroll
            for (int mt = 0; mt < 4; mt++) {
                const int mr = amr + mt * 16;
                const int ks = kt * 2 + akl;
                ldsm4(a[mt], stA + mr * 128 + ((ks ^ l7) * 16));
            }
#pragma unroll
            for (int j = 0; j < 2; j++) {
                const int nr = bnr + j * 16;
                const int ks = kt * 2 + bkl;
                ldsm4(b[j], stB + nr * 128 + ((ks ^ l7) * 16));
            }
#pragma unroll
            for (int mt = 0; mt < 4; mt++)
#pragma unroll
                for (int j = 0; j < 2; j++) {
                    mma_tf32(acc[mt][j * 2],     a[mt], &b[j][0]);
                    mma_tf32(acc[mt][j * 2 + 1], a[mt], &b[j][2]);
                }
        }
    }

    // Epilogue: c0,c1=(m + l/4, n + 2(l%4)+{0,1}), c2,c3=(m+8, ...)
    const int mw = m0 + wm * 64 + (lane >> 2);
    const int nw = n0 + wn * 32 + 2 * (lane & 3);
#pragma unroll
    for (int mt = 0; mt < 4; mt++) {
        const size_t r0 = (size_t)(mw + mt * 16) * OUT_CH;
        const size_t r1 = r0 + 8 * OUT_CH;
#pragma unroll
        for (int n8 = 0; n8 < 4; n8++) {
            const int n = nw + n8 * 8;
            const float2 bv = *reinterpret_cast<const float2*>(&bias[n]);
            float2 v0, v1;
            v0.x = acc[mt][n8][0] + bv.x;  v0.y = acc[mt][n8][1] + bv.y;
            v1.x = acc[mt][n8][2] + bv.x;  v1.y = acc[mt][n8][3] + bv.y;
            *reinterpret_cast<float2*>(&y[r0 + n]) = v0;
            *reinterpret_cast<float2*>(&y[r1 + n]) = v1;
        }
    }
}

// ---------------------------------------------------------------------------
// Launch (graph-capturable: kernel launches only, default stream)
// ---------------------------------------------------------------------------
extern "C" void kernel_launch(void* const* d_in, const int* in_sizes, int n_in,
                              void* d_out, int out_size) {
    const float* x    = (const float*)d_in[0];
    const float* w    = (const float*)d_in[1];
    const int*   rows = (const int*)  d_in[2];
    const int*   cols = (const int*)  d_in[3];
    const float* bias = (const float*)d_in[4];
    float*       y    = (float*)d_out;
    const int    nnz  = in_sizes[1];

    cudaFuncSetAttribute(k_gemm, cudaFuncAttributeMaxDynamicSharedMemorySize,
                         SMEM_TOTAL);

    k_cvt_x<<<(BATCH * IN_CH / 4) / 256, 256>>>(x);
    k_zero_w<<<(int)(((size_t)OUT_CH * IN_CH / 4) / 256), 256>>>();
    k_scatter_w<<<(nnz + 255) / 256, 256>>>(w, rows, cols, nnz);
    k_gemm<<<dim3(OUT_CH / TN, BATCH / TM), NTHREADS, SMEM_TOTAL>>>(bias, y);
}

// round 9
// speedup vs baseline: 7.3699x; 1.8041x over previous
#include <cuda_runtime.h>
#include <cuda_fp16.h>
#include <cstdint>

// Problem constants
#define IN_CH   4096
#define OUT_CH  4096
#define BATCH   8192

// GEMM tiling (fp16: 2 B/elem)
#define TM      128                  // batch rows per CTA tile
#define TN      128                  // out_ch cols per CTA tile
#define KC      64                   // K per chunk (64 fp16 = 128 B = swizzle row)
#define NCHUNK  (IN_CH / KC)         // 64
#define NSTAGE  3
#define NTHREADS 256                 // 8 warps, warp grid 2(m) x 4(n), warp tile 64x32

// smem: 3 stages of [A|B]
#define A_BYTES     (TM * 128)                     // 16384
#define B_BYTES     (TN * 128)                     // 16384
#define STAGE_BYTES (A_BYTES + B_BYTES)            // 32768
#define SMEM_TOTAL  (NSTAGE * STAGE_BYTES)         // 98304 -> 2 CTAs/SM

// SW128 swizzle (store side)
#define SWZ(o) ((o) ^ (((o) >> 3) & 0x70))

// Scratch (device globals: allocation-free per harness rules) — 96 MB
__device__ __half g_xh[(size_t)BATCH * IN_CH];    // fp16 x
__device__ __half g_wh[(size_t)OUT_CH * IN_CH];   // fp16 dense W

// ---------------------------------------------------------------------------
// PTX helpers (baseline sm_80+ instructions — valid on plain sm_103 target)
// ---------------------------------------------------------------------------
__device__ __forceinline__ uint32_t smem_u32(const void* p) {
    uint32_t a;
    asm("{ .reg .u64 t; cvta.to.shared.u64 t, %1; cvt.u32.u64 %0, t; }"
        : "=r"(a) : "l"(p));
    return a;
}
__device__ __forceinline__ void ldsm4(uint32_t* r, uint32_t addr) {
    asm volatile("ldmatrix.sync.aligned.m8n8.x4.shared.b16 {%0,%1,%2,%3}, [%4];"
                 : "=r"(r[0]), "=r"(r[1]), "=r"(r[2]), "=r"(r[3]) : "r"(addr));
}
__device__ __forceinline__ void mma_fp16(float* d, const uint32_t* a, const uint32_t* b) {
    asm volatile(
        "mma.sync.aligned.m16n8k16.row.col.f32.f16.f16.f32 "
        "{%0,%1,%2,%3}, {%4,%5,%6,%7}, {%8,%9}, {%0,%1,%2,%3};"
        : "+f"(d[0]), "+f"(d[1]), "+f"(d[2]), "+f"(d[3])
        : "r"(a[0]), "r"(a[1]), "r"(a[2]), "r"(a[3]), "r"(b[0]), "r"(b[1]));
}

// ---------------------------------------------------------------------------
// Prep kernels: fp32 -> fp16
// ---------------------------------------------------------------------------
__global__ void k_cvt_x(const float* __restrict__ x) {
    size_t i = ((size_t)blockIdx.x * 256 + threadIdx.x) * 4;
    float4 v = *reinterpret_cast<const float4*>(&x[i]);
    __half2* p = reinterpret_cast<__half2*>(&g_xh[i]);
    p[0] = __floats2half2_rn(v.x, v.y);
    p[1] = __floats2half2_rn(v.z, v.w);
}

__global__ void k_zero_w() {
    size_t i = ((size_t)blockIdx.x * 256 + threadIdx.x) * 8;   // 8 fp16 = 16 B
    *reinterpret_cast<uint4*>(&g_wh[i]) = make_uint4(0, 0, 0, 0);
}

__global__ void k_scatter_w(const float* __restrict__ w, const int* __restrict__ rows,
                            const int* __restrict__ cols, int nnz) {
    int i = blockIdx.x * 256 + threadIdx.x;
    if (i >= nnz) return;
    g_wh[(size_t)rows[i] * IN_CH + cols[i]] = __float2half_rn(w[i]);
}

// ---------------------------------------------------------------------------
// cp.async loader: one k-chunk (A 128x64 | B 128x64 fp16) into a stage.
// Row = 128 B; 16B segment s of row r stored at segment (s ^ (r & 7)).
// ---------------------------------------------------------------------------
__device__ __forceinline__ void load_chunk(uint32_t sbase, int chunk, int stage,
                                           int m0, int n0, int tid) {
    const int k0 = chunk * KC;
    const uint32_t stA = sbase + stage * STAGE_BYTES;
    const uint32_t stB = stA + A_BYTES;
#pragma unroll
    for (int it = 0; it < 2048 / NTHREADS; it++) {   // 8 iters of 16B
        int j = it * NTHREADS + tid;
        const __half* src;
        uint32_t dst;
        if (j < 1024) {                       // A: 128 rows x 8 segs
            int r = j >> 3, s = j & 7;
            src = g_xh + (size_t)(m0 + r) * IN_CH + k0 + s * 8;
            dst = stA + (uint32_t)(r * 128 + ((s ^ (r & 7)) * 16));
        } else {                              // B: 128 rows x 8 segs
            int jb = j - 1024;
            int r = jb >> 3, s = jb & 7;
            src = g_wh + (size_t)(n0 + r) * IN_CH + k0 + s * 8;
            dst = stB + (uint32_t)(r * 128 + ((s ^ (r & 7)) * 16));
        }
        asm volatile("cp.async.cg.shared.global [%0], [%1], 16;" :: "r"(dst), "l"(src));
    }
    asm volatile("cp.async.commit_group;" ::: "memory");
}

// ---------------------------------------------------------------------------
// Main GEMM: y[128 x 128] = x @ W^T + bias, single-pass fp16 mma.sync
// ---------------------------------------------------------------------------
__global__ void __launch_bounds__(NTHREADS, 2)
k_gemm(const float* __restrict__ bias, float* __restrict__ y) {
    extern __shared__ char smem[];
    const uint32_t sbase = smem_u32(smem);
    const int tid  = threadIdx.x;
    const int warp = tid >> 5;
    const int lane = tid & 31;
    const int wm   = warp >> 2;           // 0..1  (m)
    const int wn   = warp & 3;            // 0..3  (n)
    const int n0   = blockIdx.x * TN;     // x fastest -> W tiles shared per wave
    const int m0   = blockIdx.y * TM;

    // ldmatrix per-thread offsets (validated layout from the R5 bf16 kernel).
    // A x4 tiles: groups -> (m0-7,k0),(m8-15,k0),(m0-7,k+8),(m8-15,k+8)
    const uint32_t amask = (uint32_t)(lane & 7) << 4;
    uint32_t arow[4];
#pragma unroll
    for (int mt = 0; mt < 4; mt++)
        arow[mt] = (uint32_t)((wm * 64 + mt * 16 + (lane & 15)) * 128
                              + ((lane >> 4) & 1) * 16);
    // B x4 tiles: groups -> (n0-7,k0),(n0-7,k+8),(n8-15,k0),(n8-15,k+8)
    uint32_t brow[2];
#pragma unroll
    for (int nt = 0; nt < 2; nt++)
        brow[nt] = (uint32_t)((wn * 32 + nt * 16 + (lane & 7) + ((lane >> 4) & 1) * 8) * 128
                              + ((lane >> 3) & 1) * 16);

    float acc[4][4][4];
#pragma unroll
    for (int mt = 0; mt < 4; mt++)
#pragma unroll
        for (int n8 = 0; n8 < 4; n8++)
#pragma unroll
            for (int q = 0; q < 4; q++) acc[mt][n8][q] = 0.0f;

    // Prologue: prefetch chunks 0, 1 (stages 0, 1)
    load_chunk(sbase, 0, 0, m0, n0, tid);
    load_chunk(sbase, 1, 1, m0, n0, tid);

    for (int i = 0; i < NCHUNK; i++) {
        if (i < NCHUNK - 1)
            asm volatile("cp.async.wait_group 1;" ::: "memory");
        else
            asm volatile("cp.async.wait_group 0;" ::: "memory");
        __syncthreads();   // chunk i visible; stage (i+2)%3's old chunk consumed

        if (i + 2 < NCHUNK)
            load_chunk(sbase, i + 2, (i + 2) % NSTAGE, m0, n0, tid);

        const uint32_t stA = sbase + (i % NSTAGE) * STAGE_BYTES;
        const uint32_t stB = stA + A_BYTES;

#pragma unroll
        for (int kt = 0; kt < 4; kt++) {       // 4 x k16 per 64-K chunk
            const uint32_t kb = (uint32_t)(kt * 32);   // 16 fp16 = 32 B
            uint32_t a[4][4], b[2][4];
#pragma unroll
            for (int mt = 0; mt < 4; mt++)
                ldsm4(a[mt], stA + ((arow[mt] + kb) ^ amask));
#pragma unroll
            for (int nt = 0; nt < 2; nt++)
                ldsm4(b[nt], stB + ((brow[nt] + kb) ^ amask));
#pragma unroll
            for (int mt = 0; mt < 4; mt++)
#pragma unroll
                for (int nt = 0; nt < 2; nt++) {
                    mma_fp16(acc[mt][nt * 2],     a[mt], &b[nt][0]);
                    mma_fp16(acc[mt][nt * 2 + 1], a[mt], &b[nt][2]);
                }
        }
    }

    // Epilogue: c0,c1=(m + l/4, n + 2(l%4)+{0,1}), c2,c3=(m+8, ...)
    const int mw = m0 + wm * 64 + (lane >> 2);
    const int nw = n0 + wn * 32 + 2 * (lane & 3);
#pragma unroll
    for (int mt = 0; mt < 4; mt++) {
        const size_t r0 = (size_t)(mw + mt * 16) * OUT_CH;
        const size_t r1 = r0 + 8 * OUT_CH;
#pragma unroll
        for (int n8 = 0; n8 < 4; n8++) {
            const int n = nw + n8 * 8;
            const float2 bv = *reinterpret_cast<const float2*>(&bias[n]);
            float2 v0, v1;
            v0.x = acc[mt][n8][0] + bv.x;  v0.y = acc[mt][n8][1] + bv.y;
            v1.x = acc[mt][n8][2] + bv.x;  v1.y = acc[mt][n8][3] + bv.y;
            *reinterpret_cast<float2*>(&y[r0 + n]) = v0;
            *reinterpret_cast<float2*>(&y[r1 + n]) = v1;
        }
    }
}

// ---------------------------------------------------------------------------
// Launch (graph-capturable: kernel launches only, default stream)
// ---------------------------------------------------------------------------
extern "C" void kernel_launch(void* const* d_in, const int* in_sizes, int n_in,
                              void* d_out, int out_size) {
    const float* x    = (const float*)d_in[0];
    const float* w    = (const float*)d_in[1];
    const int*   rows = (const int*)  d_in[2];
    const int*   cols = (const int*)  d_in[3];
    const float* bias = (const float*)d_in[4];
    float*       y    = (float*)d_out;
    const int    nnz  = in_sizes[1];

    cudaFuncSetAttribute(k_gemm, cudaFuncAttributeMaxDynamicSharedMemorySize,
                         SMEM_TOTAL);

    k_cvt_x<<<(BATCH * IN_CH / 4) / 256, 256>>>(x);
    k_zero_w<<<(int)(((size_t)OUT_CH * IN_CH / 8) / 256), 256>>>();
    k_scatter_w<<<(nnz + 255) / 256, 256>>>(w, rows, cols, nnz);
    k_gemm<<<dim3(OUT_CH / TN, BATCH / TM), NTHREADS, SMEM_TOTAL>>>(bias, y);
}

// round 10
// speedup vs baseline: 8.1805x; 1.1100x over previous
#include <cuda_runtime.h>
#include <cuda_fp16.h>
#include <cstdint>

// Problem constants
#define IN_CH   4096
#define OUT_CH  4096
#define BATCH   8192

// GEMM tiling (fp16: 2 B/elem)
#define TM      128                  // batch rows per CTA tile
#define TN      128                  // out_ch cols per CTA tile
#define KC      64                   // K per chunk (64 fp16 = 128 B = swizzle row)
#define NCHUNK  (IN_CH / KC)         // 64
#define NSTAGE  3
#define NTHREADS 128                 // 4 warps, warp grid 2(m) x 2(n), warp tile 64x64

// smem: 3 stages of [A|B]
#define A_BYTES     (TM * 128)                     // 16384
#define B_BYTES     (TN * 128)                     // 16384
#define STAGE_BYTES (A_BYTES + B_BYTES)            // 32768
#define SMEM_TOTAL  (NSTAGE * STAGE_BYTES)         // 98304 -> 2 CTAs/SM

// Scratch (device globals: allocation-free per harness rules) — 96 MB
__device__ __half g_xh[(size_t)BATCH * IN_CH];    // fp16 x
__device__ __half g_wh[(size_t)OUT_CH * IN_CH];   // fp16 dense W

// ---------------------------------------------------------------------------
// PTX helpers (baseline sm_80+ instructions — valid on plain sm_103 target)
// ---------------------------------------------------------------------------
__device__ __forceinline__ uint32_t smem_u32(const void* p) {
    uint32_t a;
    asm("{ .reg .u64 t; cvta.to.shared.u64 t, %1; cvt.u32.u64 %0, t; }"
        : "=r"(a) : "l"(p));
    return a;
}
__device__ __forceinline__ void ldsm4(uint32_t* r, uint32_t addr) {
    asm volatile("ldmatrix.sync.aligned.m8n8.x4.shared.b16 {%0,%1,%2,%3}, [%4];"
                 : "=r"(r[0]), "=r"(r[1]), "=r"(r[2]), "=r"(r[3]) : "r"(addr));
}
__device__ __forceinline__ void mma_fp16(float* d, const uint32_t* a, const uint32_t* b) {
    asm volatile(
        "mma.sync.aligned.m16n8k16.row.col.f32.f16.f16.f32 "
        "{%0,%1,%2,%3}, {%4,%5,%6,%7}, {%8,%9}, {%0,%1,%2,%3};"
        : "+f"(d[0]), "+f"(d[1]), "+f"(d[2]), "+f"(d[3])
        : "r"(a[0]), "r"(a[1]), "r"(a[2]), "r"(a[3]), "r"(b[0]), "r"(b[1]));
}

// ---------------------------------------------------------------------------
// Prep kernels: fp32 -> fp16
// ---------------------------------------------------------------------------
__global__ void k_cvt_x(const float* __restrict__ x) {
    size_t i = ((size_t)blockIdx.x * 256 + threadIdx.x) * 4;
    float4 v = *reinterpret_cast<const float4*>(&x[i]);
    __half2* p = reinterpret_cast<__half2*>(&g_xh[i]);
    p[0] = __floats2half2_rn(v.x, v.y);
    p[1] = __floats2half2_rn(v.z, v.w);
}

__global__ void k_zero_w() {
    size_t i = ((size_t)blockIdx.x * 256 + threadIdx.x) * 8;   // 8 fp16 = 16 B
    *reinterpret_cast<uint4*>(&g_wh[i]) = make_uint4(0, 0, 0, 0);
}

__global__ void k_scatter_w(const float* __restrict__ w, const int* __restrict__ rows,
                            const int* __restrict__ cols, int nnz) {
    int i = blockIdx.x * 256 + threadIdx.x;
    if (i >= nnz) return;
    g_wh[(size_t)rows[i] * IN_CH + cols[i]] = __float2half_rn(w[i]);
}

// ---------------------------------------------------------------------------
// cp.async loader: one k-chunk (A 128x64 | B 128x64 fp16) into a stage.
// Row = 128 B; 16B segment s of row r stored at segment (s ^ (r & 7)).
// ---------------------------------------------------------------------------
__device__ __forceinline__ void load_chunk(uint32_t sbase, int chunk, int stage,
                                           int m0, int n0, int tid) {
    const int k0 = chunk * KC;
    const uint32_t stA = sbase + stage * STAGE_BYTES;
    const uint32_t stB = stA + A_BYTES;
#pragma unroll
    for (int it = 0; it < 2048 / NTHREADS; it++) {   // 16 iters of 16B
        int j = it * NTHREADS + tid;
        const __half* src;
        uint32_t dst;
        if (j < 1024) {                       // A: 128 rows x 8 segs
            int r = j >> 3, s = j & 7;
            src = g_xh + (size_t)(m0 + r) * IN_CH + k0 + s * 8;
            dst = stA + (uint32_t)(r * 128 + ((s ^ (r & 7)) * 16));
        } else {                              // B: 128 rows x 8 segs
            int jb = j - 1024;
            int r = jb >> 3, s = jb & 7;
            src = g_wh + (size_t)(n0 + r) * IN_CH + k0 + s * 8;
            dst = stB + (uint32_t)(r * 128 + ((s ^ (r & 7)) * 16));
        }
        asm volatile("cp.async.cg.shared.global [%0], [%1], 16;" :: "r"(dst), "l"(src));
    }
    asm volatile("cp.async.commit_group;" ::: "memory");
}

// ---------------------------------------------------------------------------
// Main GEMM: y[128 x 128] = x @ W^T + bias, single-pass fp16 mma.sync.
// 4 warps, warp tile 64x64: 8 LDSM.x4 feed 32 MMAs per kt (128 B/MMA).
// ---------------------------------------------------------------------------
__global__ void __launch_bounds__(NTHREADS, 2)
k_gemm(const float* __restrict__ bias, float* __restrict__ y) {
    extern __shared__ char smem[];
    const uint32_t sbase = smem_u32(smem);
    const int tid  = threadIdx.x;
    const int warp = tid >> 5;
    const int lane = tid & 31;
    const int wm   = warp >> 1;           // 0..1  (m)
    const int wn   = warp & 1;            // 0..1  (n)
    const int n0   = blockIdx.x * TN;     // x fastest -> W tiles shared per wave
    const int m0   = blockIdx.y * TM;

    // ldmatrix per-thread offsets (layouts validated in R5/R6/R8).
    // A x4 tiles: groups -> (m0-7,k0),(m8-15,k0),(m0-7,k+8),(m8-15,k+8)
    const uint32_t amask = (uint32_t)(lane & 7) << 4;
    uint32_t arow[4];
#pragma unroll
    for (int mt = 0; mt < 4; mt++)
        arow[mt] = (uint32_t)((wm * 64 + mt * 16 + (lane & 15)) * 128
                              + ((lane >> 4) & 1) * 16);
    // B x4 tiles: groups -> (n0-7,k0),(n0-7,k+8),(n8-15,k0),(n8-15,k+8)
    uint32_t brow[4];
#pragma unroll
    for (int nt = 0; nt < 4; nt++)
        brow[nt] = (uint32_t)((wn * 64 + nt * 16 + (lane & 7) + ((lane >> 4) & 1) * 8) * 128
                              + ((lane >> 3) & 1) * 16);

    float acc[4][8][4];
#pragma unroll
    for (int mt = 0; mt < 4; mt++)
#pragma unroll
        for (int n8 = 0; n8 < 8; n8++)
#pragma unroll
            for (int q = 0; q < 4; q++) acc[mt][n8][q] = 0.0f;

    // Prologue: prefetch chunks 0, 1 (stages 0, 1)
    load_chunk(sbase, 0, 0, m0, n0, tid);
    load_chunk(sbase, 1, 1, m0, n0, tid);

    for (int i = 0; i < NCHUNK; i++) {
        if (i < NCHUNK - 1)
            asm volatile("cp.async.wait_group 1;" ::: "memory");
        else
            asm volatile("cp.async.wait_group 0;" ::: "memory");
        __syncthreads();   // chunk i visible; stage (i+2)%3's old chunk consumed

        if (i + 2 < NCHUNK)
            load_chunk(sbase, i + 2, (i + 2) % NSTAGE, m0, n0, tid);

        const uint32_t stA = sbase + (i % NSTAGE) * STAGE_BYTES;
        const uint32_t stB = stA + A_BYTES;

#pragma unroll
        for (int kt = 0; kt < 4; kt++) {       // 4 x k16 per 64-K chunk
            const uint32_t kb = (uint32_t)(kt * 32);   // 16 fp16 = 32 B
            uint32_t a[4][4], b[4][4];
#pragma unroll
            for (int mt = 0; mt < 4; mt++)
                ldsm4(a[mt], stA + ((arow[mt] + kb) ^ amask));
#pragma unroll
            for (int nt = 0; nt < 4; nt++)
                ldsm4(b[nt], stB + ((brow[nt] + kb) ^ amask));
#pragma unroll
            for (int mt = 0; mt < 4; mt++)
#pragma unroll
                for (int nt = 0; nt < 4; nt++) {
                    mma_fp16(acc[mt][nt * 2],     a[mt], &b[nt][0]);
                    mma_fp16(acc[mt][nt * 2 + 1], a[mt], &b[nt][2]);
                }
        }
    }

    // Epilogue: c0,c1=(m + l/4, n + 2(l%4)+{0,1}), c2,c3=(m+8, ...)
    const int mw = m0 + wm * 64 + (lane >> 2);
    const int nw = n0 + wn * 64 + 2 * (lane & 3);
#pragma unroll
    for (int mt = 0; mt < 4; mt++) {
        const size_t r0 = (size_t)(mw + mt * 16) * OUT_CH;
        const size_t r1 = r0 + 8 * OUT_CH;
#pragma unroll
        for (int n8 = 0; n8 < 8; n8++) {
            const int n = nw + n8 * 8;
            const float2 bv = *reinterpret_cast<const float2*>(&bias[n]);
            float2 v0, v1;
            v0.x = acc[mt][n8][0] + bv.x;  v0.y = acc[mt][n8][1] + bv.y;
            v1.x = acc[mt][n8][2] + bv.x;  v1.y = acc[mt][n8][3] + bv.y;
            *reinterpret_cast<float2*>(&y[r0 + n]) = v0;
            *reinterpret_cast<float2*>(&y[r1 + n]) = v1;
        }
    }
}

// ---------------------------------------------------------------------------
// Launch (graph-capturable: kernel launches only, default stream)
// ---------------------------------------------------------------------------
extern "C" void kernel_launch(void* const* d_in, const int* in_sizes, int n_in,
                              void* d_out, int out_size) {
    const float* x    = (const float*)d_in[0];
    const float* w    = (const float*)d_in[1];
    const int*   rows = (const int*)  d_in[2];
    const int*   cols = (const int*)  d_in[3];
    const float* bias = (const float*)d_in[4];
    float*       y    = (float*)d_out;
    const int    nnz  = in_sizes[1];

    cudaFuncSetAttribute(k_gemm, cudaFuncAttributeMaxDynamicSharedMemorySize,
                         SMEM_TOTAL);

    k_cvt_x<<<(BATCH * IN_CH / 4) / 256, 256>>>(x);
    k_zero_w<<<(int)(((size_t)OUT_CH * IN_CH / 8) / 256), 256>>>();
    k_scatter_w<<<(nnz + 255) / 256, 256>>>(w, rows, cols, nnz);
    k_gemm<<<dim3(OUT_CH / TN, BATCH / TM), NTHREADS, SMEM_TOTAL>>>(bias, y);
}